// round 17
// baseline (speedup 1.0000x reference)
#include <cuda_runtime.h>
#include <cstdint>

// out[b,h,w,:] = graph_lstm_output[b, slic[b,h,w]-1, :]
//   graph_lstm_output: [B=4, S=256, C=128] f32   (d_in[0])
//   slic_output:       [B=4, 512, 512] i32       (d_in[1])
//
// R16 WIN: L2-prefetch of slic (write-only DRAM stream) -> 78.0us, DRAM 78.5%.
// R17: with slic now an L2 hit (~250 cyc, not ~600 DRAM), the per-chain
// latency halved -- retry UNROLL=8 (R5's failure was chains too long for the
// register-limited interleave; that constraint is now relaxed).

static constexpr unsigned F4_PER_BATCH = 1u << 23;        // 2^18 pix * 32 f4
static constexpr int UNROLL = 8;
static constexpr unsigned CHUNK = F4_PER_BATCH / UNROLL;  // 2^20 f4
static constexpr unsigned THREADS_TOTAL = 1u << 22;       // 2^25 f4 / 8

// ---------------------------------------------------------------------------
// Kernel A: pull slic (4 MB) + table (0.5 MB) into L2. One prefetch per
// 128 B line: 32768 + 4096 = 36864 threads. L2-only — does not touch L1.
// ---------------------------------------------------------------------------
__global__ __launch_bounds__(256)
void l2_prefetch(const int* __restrict__ slic, const float* __restrict__ src)
{
    unsigned t = blockIdx.x * blockDim.x + threadIdx.x;
    if (t < 32768u) {
        const char* p = reinterpret_cast<const char*>(slic) + (size_t)t * 128;
        asm volatile("prefetch.global.L2 [%0];" :: "l"(p));
    } else if (t < 36864u) {
        unsigned u = t - 32768u;
        const char* p = reinterpret_cast<const char*>(src) + (size_t)u * 128;
        asm volatile("prefetch.global.L2 [%0];" :: "l"(p));
    }
}

// ---------------------------------------------------------------------------
// Kernel B: batch-local gather, 8 independent chains per thread.
// ---------------------------------------------------------------------------
__global__ __launch_bounds__(256)
void convert2image_l1u8(const float4* __restrict__ src,   // [4*256, 32] f4
                        const int*    __restrict__ slic,  // [4, 2^18]
                        float4*       __restrict__ out)   // [4, 2^18, 32]
{
    const unsigned t = blockIdx.x * blockDim.x + threadIdx.x;  // [0, 2^22)

    const unsigned b    = t >> 20;             // batch: 2^20 threads per batch
    const unsigned loc  = t & (CHUNK - 1u);    // local f4 base within batch
    const unsigned lane = loc & 31;            // CHUNK is 32-aligned

    const int*    sl = slic + (b << 18);
    const float4* tb = src  + (b << 13);       // this batch's 128 KB table
    float4*       ob = out  + (b << 23);

    // Phase 1: 8 independent slic loads. __ldcs: L1-bypassing (table owns
    // L1), L2 hits thanks to the prefetch kernel (~250 cyc chains).
    const float4* rowp[UNROLL];
    #pragma unroll
    for (int i = 0; i < UNROLL; i++) {
        unsigned pix = (loc + (unsigned)i * CHUNK) >> 5;
        int seg = __ldcs(&sl[pix]) - 1;        // 0-based segment
        rowp[i] = tb + (((unsigned)seg) << 5); // seg * 32 float4
    }

    // Phase 2: 8 independent gathers from the batch-local L1-hot table.
    float4 v[UNROLL];
    #pragma unroll
    for (int i = 0; i < UNROLL; i++)
        v[i] = __ldg(&rowp[i][lane]);

    // Phase 3: 8 coalesced streaming stores (write-once, evict-first).
    #pragma unroll
    for (int i = 0; i < UNROLL; i++)
        __stcs(&ob[loc + (unsigned)i * CHUNK], v[i]);
}

extern "C" void kernel_launch(void* const* d_in, const int* in_sizes, int n_in,
                              void* d_out, int out_size)
{
    const float4* src  = (const float4*)d_in[0];
    const int*    slic = (const int*)d_in[1];
    float4*       out  = (float4*)d_out;

    l2_prefetch<<<144, 256>>>(slic, (const float*)src);

    const int threads = 256;
    const int blocks  = THREADS_TOTAL / threads;   // 16384
    convert2image_l1u8<<<blocks, threads>>>(src, slic, out);
}